// round 11
// baseline (speedup 1.0000x reference)
#include <cuda_runtime.h>
#include <cuda_fp16.h>
#include <math.h>

#define T_STEPS 4096
#define IN_SZ   512
#define H1      1024
#define H2      2048
#define OUT_SZ  512
#define NCTA    128

#define CSM1    1024    // lstm1: all columns SMEM-resident
#define CSM2    1664    // lstm2: 13/16 of columns SMEM-resident

// ---------------- device scratch (static, no allocation) ----------------
__device__ float g_pre1[T_STEPS * 4 * H1];        //  64 MB
__device__ float g_pre2[T_STEPS * 4 * H2];        // 128 MB
__device__ float g_hist1[(T_STEPS + 1) * H1];     //  slot t = h[t-1], slot 0 = zeros
__device__ float g_hist2[(T_STEPS + 1) * H2];
__device__ float g_mid[2 * OUT_SZ];
__device__ unsigned g_flags1[T_STEPS * NCTA];     // per-CTA step flags (2 MB)
__device__ unsigned g_flags2[T_STEPS * NCTA];

// fp16 copies of recurrent weights, packed 4 halfs per uint2
__device__ uint2 g_whh1h[(size_t)4 * H1 * H1 / 4];   //  8 MB
__device__ uint2 g_whh2h[(size_t)4 * H2 * H2 / 4];   // 32 MB

// ---------------- helpers ----------------
__device__ __forceinline__ unsigned ld_acq_u32(const unsigned* p) {
    unsigned v;
    asm volatile("ld.acquire.gpu.global.u32 %0, [%1];" : "=r"(v) : "l"(p));
    return v;
}

__device__ __forceinline__ void st_rel_u32(unsigned* p, unsigned v) {
    asm volatile("st.release.gpu.global.u32 [%0], %1;" :: "l"(p), "r"(v));
}

__device__ __forceinline__ float4 ld_cg_f4(const float4* p) {
    float4 v;
    asm volatile("ld.global.cg.v4.f32 {%0,%1,%2,%3}, [%4];"
                 : "=f"(v.x), "=f"(v.y), "=f"(v.z), "=f"(v.w) : "l"(p));
    return v;
}

__device__ __forceinline__ void st_cg_f32(float* p, float v) {
    asm volatile("st.global.cg.f32 [%0], %1;" :: "l"(p), "f"(v));
}

__device__ __forceinline__ float sigmoidf_(float x) {
    return 1.0f / (1.0f + expf(-x));
}

// ---------------- init: zero flags + h0 slots (runs every replay) ----------------
__global__ void init_kernel() {
    const int total = T_STEPS * NCTA;
    for (int i = blockIdx.x * blockDim.x + threadIdx.x;
         i < total; i += gridDim.x * blockDim.x) {
        g_flags1[i] = 0u;
        g_flags2[i] = 0u;
        if (i < H1) g_hist1[i] = 0.0f;
        if (i < H2) g_hist2[i] = 0.0f;
    }
}

// ---------------- convert recurrent weights fp32 -> fp16 (once per replay) ----------------
__global__ void convert_w_kernel(const float* __restrict__ w1,
                                 const float* __restrict__ w2) {
    const size_t n1 = (size_t)4 * H1 * H1 / 4;
    const size_t n2 = (size_t)4 * H2 * H2 / 4;
    for (size_t i = (size_t)blockIdx.x * blockDim.x + threadIdx.x;
         i < n1 + n2; i += (size_t)gridDim.x * blockDim.x) {
        float4 v = (i < n1) ? ((const float4*)w1)[i] : ((const float4*)w2)[i - n1];
        __half2 lo = __floats2half2_rn(v.x, v.y);
        __half2 hi = __floats2half2_rn(v.z, v.w);
        uint2 o;
        o.x = *reinterpret_cast<unsigned*>(&lo);
        o.y = *reinterpret_cast<unsigned*>(&hi);
        if (i < n1) g_whh1h[i] = o;
        else        g_whh2h[i - n1] = o;
    }
}

// ---------------- input-projection GEMM: C[M,N] = X[M,K] * W[N,K]^T + ba + bb ----------------
template <int MODE>
__global__ void __launch_bounds__(256, 2)
gemm_bias_kernel(const float* __restrict__ Xin, const float* __restrict__ W,
                 const float* __restrict__ ba, const float* __restrict__ bb,
                 int N, int K) {
    float* C = (MODE == 0) ? g_pre1 : g_pre2;
    const float* X = (MODE == 0) ? Xin : (g_hist1 + H1);

    __shared__ float Xs[16][64];
    __shared__ float Ws[16][64];

    int tid = threadIdx.x;
    int tx = tid & 15;
    int ty = tid >> 4;
    int n0 = blockIdx.x * 64;
    int m0 = blockIdx.y * 64;

    float acc[4][4];
#pragma unroll
    for (int i = 0; i < 4; i++)
#pragma unroll
        for (int j = 0; j < 4; j++) acc[i][j] = 0.0f;

    for (int kk = 0; kk < K; kk += 16) {
#pragma unroll
        for (int i = tid; i < 1024; i += 256) {
            int r = i >> 4;
            int k = i & 15;
            Xs[k][r] = X[(size_t)(m0 + r) * K + kk + k];
            Ws[k][r] = W[(size_t)(n0 + r) * K + kk + k];
        }
        __syncthreads();
#pragma unroll
        for (int k = 0; k < 16; k++) {
            float4 a = *(const float4*)&Xs[k][ty * 4];
            float4 b = *(const float4*)&Ws[k][tx * 4];
            float av[4] = {a.x, a.y, a.z, a.w};
            float bv[4] = {b.x, b.y, b.z, b.w};
#pragma unroll
            for (int i = 0; i < 4; i++)
#pragma unroll
                for (int j = 0; j < 4; j++) acc[i][j] = fmaf(av[i], bv[j], acc[i][j]);
        }
        __syncthreads();
    }

#pragma unroll
    for (int i = 0; i < 4; i++) {
        int m = m0 + ty * 4 + i;
#pragma unroll
        for (int j = 0; j < 4; j++) {
            int n = n0 + tx * 4 + j;
            C[(size_t)m * N + n] = acc[i][j] + ba[n] + bb[n];
        }
    }
}

// ---------------- persistent LSTM recurrence ----------------
// 128 CTAs, single co-resident wave. One warp owns one hidden unit; cell state c
// lives in a lane-0 register across all 4096 steps. h history is write-once.
// Weights: columns [0,CSM) live in SMEM (preloaded once); columns [CSM,HD)
// streamed from L2 each step, prefetched into regs BEFORE the barrier wait.
// Barrier: per-CTA flag words (distinct L2 addresses) -> no atomic serialization.
template <int HD, int PHASE, int CSM>
__global__ void __launch_bounds__(HD / 4, 1)
lstm_kernel() {
    constexpr int WARPS = HD / 128;          // warps per CTA = units per CTA
    constexpr int NSM   = CSM / 4;           // smem uint2 per gate row
    constexpr int NST   = (HD - CSM) / 4;    // streamed uint2 per gate row
    constexpr int ISM   = NSM / 32;
    constexpr int IST   = NST / 32;

    const float* pre  = (PHASE == 0) ? g_pre1  : g_pre2;
    float*       hist = (PHASE == 0) ? g_hist1 : g_hist2;
    unsigned*    flags= (PHASE == 0) ? g_flags1: g_flags2;
    const uint2* whh  = (PHASE == 0) ? g_whh1h : g_whh2h;

    extern __shared__ char smem_raw[];
    uint2*  wsm = (uint2*)smem_raw;                                  // [WARPS*4*NSM]
    float4* hs  = (float4*)(smem_raw + (size_t)WARPS * 4 * NSM * 8); // [HD/4]

    int tid  = threadIdx.x;
    int wid  = tid >> 5;
    int lane = tid & 31;
    int u = blockIdx.x * WARPS + wid;

    // ---- preload SMEM-resident weight columns (once) ----
    for (int idx = tid; idx < WARPS * 4 * NSM; idx += blockDim.x) {
        int row = idx / NSM;             // w*4 + g
        int col = idx - row * NSM;
        int w = row >> 2, g = row & 3;
        int uu = blockIdx.x * WARPS + w;
        wsm[idx] = whh[(size_t)(g * HD + uu) * (HD / 4) + col];
    }
    __syncthreads();

    // streamed-region global pointers (per warp, per gate)
    const uint2* wst0 = whh + (size_t)(0 * HD + u) * (HD / 4) + NSM;
    const uint2* wst1 = whh + (size_t)(1 * HD + u) * (HD / 4) + NSM;
    const uint2* wst2 = whh + (size_t)(2 * HD + u) * (HD / 4) + NSM;
    const uint2* wst3 = whh + (size_t)(3 * HD + u) * (HD / 4) + NSM;

    const uint2* wsm0 = wsm + (size_t)(wid * 4 + 0) * NSM;
    const uint2* wsm1 = wsm + (size_t)(wid * 4 + 1) * NSM;
    const uint2* wsm2 = wsm + (size_t)(wid * 4 + 2) * NSM;
    const uint2* wsm3 = wsm + (size_t)(wid * 4 + 3) * NSM;

    float c = 0.0f;

    for (int t = 0; t < T_STEPS; t++) {
        // ---- prefetch streamed weights (step-invariant, no barrier dependency) ----
        uint2 sw0[IST > 0 ? IST : 1], sw1[IST > 0 ? IST : 1];
        uint2 sw2[IST > 0 ? IST : 1], sw3[IST > 0 ? IST : 1];
        if (IST > 0) {
#pragma unroll
            for (int i = 0; i < IST; i++) {
                int j = (i << 5) + lane;
                sw0[i] = wst0[j]; sw1[i] = wst1[j];
                sw2[i] = wst2[j]; sw3[i] = wst3[j];
            }
        }

        // ---- distributed barrier: thread p waits on CTA p's flag for step t-1 ----
        if (t > 0 && tid < NCTA) {
            while (ld_acq_u32(&flags[(t - 1) * NCTA + tid]) == 0u) {
                __nanosleep(32);
            }
        }
        __syncthreads();

        // ---- stage h_prev (slot t) into SMEM, L1-bypassed ----
        hs[tid] = ld_cg_f4((const float4*)(hist + (size_t)t * HD) + tid);
        __syncthreads();

        // ---- gate dot products: SMEM part ----
        float a0 = 0.f, a1 = 0.f, a2 = 0.f, a3 = 0.f;
#pragma unroll
        for (int i = 0; i < ISM; i++) {
            int c4 = (i << 5) + lane;
            float4 h4 = hs[c4];
            {
                uint2 p = wsm0[c4];
                float2 lo = __half22float2(*reinterpret_cast<__half2*>(&p.x));
                float2 hi = __half22float2(*reinterpret_cast<__half2*>(&p.y));
                a0 = fmaf(lo.x, h4.x, a0); a0 = fmaf(lo.y, h4.y, a0);
                a0 = fmaf(hi.x, h4.z, a0); a0 = fmaf(hi.y, h4.w, a0);
            }
            {
                uint2 p = wsm1[c4];
                float2 lo = __half22float2(*reinterpret_cast<__half2*>(&p.x));
                float2 hi = __half22float2(*reinterpret_cast<__half2*>(&p.y));
                a1 = fmaf(lo.x, h4.x, a1); a1 = fmaf(lo.y, h4.y, a1);
                a1 = fmaf(hi.x, h4.z, a1); a1 = fmaf(hi.y, h4.w, a1);
            }
            {
                uint2 p = wsm2[c4];
                float2 lo = __half22float2(*reinterpret_cast<__half2*>(&p.x));
                float2 hi = __half22float2(*reinterpret_cast<__half2*>(&p.y));
                a2 = fmaf(lo.x, h4.x, a2); a2 = fmaf(lo.y, h4.y, a2);
                a2 = fmaf(hi.x, h4.z, a2); a2 = fmaf(hi.y, h4.w, a2);
            }
            {
                uint2 p = wsm3[c4];
                float2 lo = __half22float2(*reinterpret_cast<__half2*>(&p.x));
                float2 hi = __half22float2(*reinterpret_cast<__half2*>(&p.y));
                a3 = fmaf(lo.x, h4.x, a3); a3 = fmaf(lo.y, h4.y, a3);
                a3 = fmaf(hi.x, h4.z, a3); a3 = fmaf(hi.y, h4.w, a3);
            }
        }
        // ---- streamed part (registers already loaded) ----
        if (IST > 0) {
#pragma unroll
            for (int i = 0; i < IST; i++) {
                int c4 = NSM + (i << 5) + lane;
                float4 h4 = hs[c4];
                {
                    float2 lo = __half22float2(*reinterpret_cast<__half2*>(&sw0[i].x));
                    float2 hi = __half22float2(*reinterpret_cast<__half2*>(&sw0[i].y));
                    a0 = fmaf(lo.x, h4.x, a0); a0 = fmaf(lo.y, h4.y, a0);
                    a0 = fmaf(hi.x, h4.z, a0); a0 = fmaf(hi.y, h4.w, a0);
                }
                {
                    float2 lo = __half22float2(*reinterpret_cast<__half2*>(&sw1[i].x));
                    float2 hi = __half22float2(*reinterpret_cast<__half2*>(&sw1[i].y));
                    a1 = fmaf(lo.x, h4.x, a1); a1 = fmaf(lo.y, h4.y, a1);
                    a1 = fmaf(hi.x, h4.z, a1); a1 = fmaf(hi.y, h4.w, a1);
                }
                {
                    float2 lo = __half22float2(*reinterpret_cast<__half2*>(&sw2[i].x));
                    float2 hi = __half22float2(*reinterpret_cast<__half2*>(&sw2[i].y));
                    a2 = fmaf(lo.x, h4.x, a2); a2 = fmaf(lo.y, h4.y, a2);
                    a2 = fmaf(hi.x, h4.z, a2); a2 = fmaf(hi.y, h4.w, a2);
                }
                {
                    float2 lo = __half22float2(*reinterpret_cast<__half2*>(&sw3[i].x));
                    float2 hi = __half22float2(*reinterpret_cast<__half2*>(&sw3[i].y));
                    a3 = fmaf(lo.x, h4.x, a3); a3 = fmaf(lo.y, h4.y, a3);
                    a3 = fmaf(hi.x, h4.z, a3); a3 = fmaf(hi.y, h4.w, a3);
                }
            }
        }
#pragma unroll
        for (int off = 16; off > 0; off >>= 1) {
            a0 += __shfl_xor_sync(0xFFFFFFFFu, a0, off);
            a1 += __shfl_xor_sync(0xFFFFFFFFu, a1, off);
            a2 += __shfl_xor_sync(0xFFFFFFFFu, a2, off);
            a3 += __shfl_xor_sync(0xFFFFFFFFu, a3, off);
        }

        // ---- state update + publish h into write-once slot t+1 ----
        if (lane == 0) {
            const float* prow = pre + (size_t)t * (4 * HD);
            float pi = prow[0 * HD + u] + a0;
            float pf = prow[1 * HD + u] + a1;
            float pg = prow[2 * HD + u] + a2;
            float po = prow[3 * HD + u] + a3;
            float iv = sigmoidf_(pi);
            float fv = sigmoidf_(pf);
            float gv = tanhf(pg);
            float ov = sigmoidf_(po);
            c = fv * c + iv * gv;
            float h = ov * tanhf(c);
            st_cg_f32(hist + (size_t)(t + 1) * HD + u, h);
        }

        // ---- release: each storer drains its own store; CTA's flag gets ONE store ----
        __threadfence();
        __syncthreads();
        if (tid == 0) {
            st_rel_u32(&flags[t * NCTA + blockIdx.x], 1u);
        }
    }
}

// ---------------- head: two matvecs on final h2 (slot T of g_hist2) ----------------
__global__ void __launch_bounds__(256) head1_kernel(const float* __restrict__ w,
                                                    const float* __restrict__ b) {
    int wid = threadIdx.x >> 5, lane = threadIdx.x & 31;
    int o = blockIdx.x * 8 + wid;
    const float4* wr = (const float4*)(w + (size_t)o * H2);
    const float4* hv = (const float4*)(g_hist2 + (size_t)T_STEPS * H2);
    float a = 0.f;
#pragma unroll
    for (int i = 0; i < 16; i++) {
        float4 W4 = wr[(i << 5) + lane];
        float4 Hh = hv[(i << 5) + lane];
        a = fmaf(W4.x, Hh.x, a); a = fmaf(W4.y, Hh.y, a);
        a = fmaf(W4.z, Hh.z, a); a = fmaf(W4.w, Hh.w, a);
    }
#pragma unroll
    for (int off = 16; off > 0; off >>= 1) a += __shfl_xor_sync(0xFFFFFFFFu, a, off);
    if (lane == 0) g_mid[o] = a + b[o];
}

__global__ void __launch_bounds__(256) head2_kernel(const float* __restrict__ w,
                                                    const float* __restrict__ b,
                                                    float* __restrict__ out) {
    int wid = threadIdx.x >> 5, lane = threadIdx.x & 31;
    int o = blockIdx.x * 8 + wid;
    const float4* wr = (const float4*)(w + (size_t)o * (2 * OUT_SZ));
    const float4* mv = (const float4*)(g_mid);
    float a = 0.f;
#pragma unroll
    for (int i = 0; i < 8; i++) {
        float4 W4 = wr[(i << 5) + lane];
        float4 Mm = mv[(i << 5) + lane];
        a = fmaf(W4.x, Mm.x, a); a = fmaf(W4.y, Mm.y, a);
        a = fmaf(W4.z, Mm.z, a); a = fmaf(W4.w, Mm.w, a);
    }
#pragma unroll
    for (int off = 16; off > 0; off >>= 1) a += __shfl_xor_sync(0xFFFFFFFFu, a, off);
    if (lane == 0) out[o] = a + b[o];
}

// ---------------- launch ----------------
extern "C" void kernel_launch(void* const* d_in, const int* in_sizes, int n_in,
                              void* d_out, int out_size) {
    const float* input_seq = (const float*)d_in[0];
    const float* w_ih1     = (const float*)d_in[1];
    const float* w_hh1     = (const float*)d_in[2];
    const float* b_ih1     = (const float*)d_in[3];
    const float* b_hh1     = (const float*)d_in[4];
    const float* w_ih2     = (const float*)d_in[5];
    const float* w_hh2     = (const float*)d_in[6];
    const float* b_ih2     = (const float*)d_in[7];
    const float* b_hh2     = (const float*)d_in[8];
    const float* w_l1      = (const float*)d_in[9];
    const float* b_l1      = (const float*)d_in[10];
    const float* w_l2      = (const float*)d_in[11];
    const float* b_l2      = (const float*)d_in[12];
    float* out = (float*)d_out;

    constexpr int SMEM1 = (H1 / 128) * 4 * (CSM1 / 4) * 8 + H1 * 4;   //  69632 B
    constexpr int SMEM2 = (H2 / 128) * 4 * (CSM2 / 4) * 8 + H2 * 4;   // 221184 B

    static bool attr_done = false;
    if (!attr_done) {
        cudaFuncSetAttribute(lstm_kernel<H1, 0, CSM1>,
                             cudaFuncAttributeMaxDynamicSharedMemorySize, SMEM1);
        cudaFuncSetAttribute(lstm_kernel<H2, 1, CSM2>,
                             cudaFuncAttributeMaxDynamicSharedMemorySize, SMEM2);
        attr_done = true;
    }

    // 1) reset flags + zero h0 slots; convert recurrent weights to fp16
    init_kernel<<<1024, 256>>>();
    convert_w_kernel<<<4096, 256>>>(w_hh1, w_hh2);

    // 2) lstm1 input projection: g_pre1[T, 4*H1]
    {
        dim3 grid(4 * H1 / 64, T_STEPS / 64);
        gemm_bias_kernel<0><<<grid, 256>>>(input_seq, w_ih1, b_ih1, b_hh1,
                                           4 * H1, IN_SZ);
    }

    // 3) lstm1 recurrence (persistent, 128 CTAs x 256 threads, full SMEM weights)
    lstm_kernel<H1, 0, CSM1><<<NCTA, H1 / 4, SMEM1>>>();

    // 4) lstm2 input projection: g_pre2[T, 4*H2] from h1 history
    {
        dim3 grid(4 * H2 / 64, T_STEPS / 64);
        gemm_bias_kernel<1><<<grid, 256>>>(nullptr, w_ih2, b_ih2, b_hh2,
                                           4 * H2, H1);
    }

    // 5) lstm2 recurrence (persistent, 128 CTAs x 512 threads, 13/16 SMEM weights)
    lstm_kernel<H2, 1, CSM2><<<NCTA, H2 / 4, SMEM2>>>();

    // 6) head on final h2
    head1_kernel<<<128, 256>>>(w_l1, b_l1);
    head2_kernel<<<64, 256>>>(w_l2, b_l2, out);
}

// round 12
// speedup vs baseline: 1.7358x; 1.7358x over previous
#include <cuda_runtime.h>
#include <cuda_fp16.h>
#include <math.h>

#define T_STEPS 4096
#define IN_SZ   512
#define H1      1024
#define H2      2048
#define OUT_SZ  512
#define NCTA    128

#define CSM1    1024    // lstm1: all columns SMEM-resident
#define CSM2    1664    // lstm2: 13/16 of columns SMEM-resident

#define FPAD    32      // flag padding: 32 u32 = 128 B -> one L2 line per CTA flag

// ---------------- device scratch (static, no allocation) ----------------
__device__ float g_pre1[T_STEPS * 4 * H1];        //  64 MB
__device__ float g_pre2[T_STEPS * 4 * H2];        // 128 MB
__device__ float g_hist1[(T_STEPS + 1) * H1];     //  slot t = h[t-1], slot 0 = zeros
__device__ float g_hist2[(T_STEPS + 1) * H2];
__device__ float g_mid[2 * OUT_SZ];
__device__ unsigned g_flags1[NCTA * FPAD];        // monotonic step counters, line-padded
__device__ unsigned g_flags2[NCTA * FPAD];

// fp16 copies of recurrent weights, packed 4 halfs per uint2
__device__ uint2 g_whh1h[(size_t)4 * H1 * H1 / 4];   //  8 MB
__device__ uint2 g_whh2h[(size_t)4 * H2 * H2 / 4];   // 32 MB

// ---------------- helpers ----------------
__device__ __forceinline__ unsigned ld_acq_u32(const unsigned* p) {
    unsigned v;
    asm volatile("ld.acquire.gpu.global.u32 %0, [%1];" : "=r"(v) : "l"(p));
    return v;
}

__device__ __forceinline__ void st_rel_u32(unsigned* p, unsigned v) {
    asm volatile("st.release.gpu.global.u32 [%0], %1;" :: "l"(p), "r"(v));
}

__device__ __forceinline__ float4 ld_cg_f4(const float4* p) {
    float4 v;
    asm volatile("ld.global.cg.v4.f32 {%0,%1,%2,%3}, [%4];"
                 : "=f"(v.x), "=f"(v.y), "=f"(v.z), "=f"(v.w) : "l"(p));
    return v;
}

__device__ __forceinline__ void st_cg_f32(float* p, float v) {
    asm volatile("st.global.cg.f32 [%0], %1;" :: "l"(p), "f"(v));
}

__device__ __forceinline__ float sigmoidf_(float x) {
    return 1.0f / (1.0f + expf(-x));
}

// ---------------- init: zero flags + h0 slots (runs every replay) ----------------
__global__ void init_kernel() {
    int i = blockIdx.x * blockDim.x + threadIdx.x;
    if (i < NCTA * FPAD) { g_flags1[i] = 0u; g_flags2[i] = 0u; }
    if (i < H1) g_hist1[i] = 0.0f;
    if (i < H2) g_hist2[i] = 0.0f;
}

// ---------------- convert recurrent weights fp32 -> fp16 (once per replay) ----------------
__global__ void convert_w_kernel(const float* __restrict__ w1,
                                 const float* __restrict__ w2) {
    const size_t n1 = (size_t)4 * H1 * H1 / 4;
    const size_t n2 = (size_t)4 * H2 * H2 / 4;
    for (size_t i = (size_t)blockIdx.x * blockDim.x + threadIdx.x;
         i < n1 + n2; i += (size_t)gridDim.x * blockDim.x) {
        float4 v = (i < n1) ? ((const float4*)w1)[i] : ((const float4*)w2)[i - n1];
        __half2 lo = __floats2half2_rn(v.x, v.y);
        __half2 hi = __floats2half2_rn(v.z, v.w);
        uint2 o;
        o.x = *reinterpret_cast<unsigned*>(&lo);
        o.y = *reinterpret_cast<unsigned*>(&hi);
        if (i < n1) g_whh1h[i] = o;
        else        g_whh2h[i - n1] = o;
    }
}

// ---------------- input-projection GEMM: C[M,N] = X[M,K] * W[N,K]^T + ba + bb ----------------
template <int MODE>
__global__ void __launch_bounds__(256, 2)
gemm_bias_kernel(const float* __restrict__ Xin, const float* __restrict__ W,
                 const float* __restrict__ ba, const float* __restrict__ bb,
                 int N, int K) {
    float* C = (MODE == 0) ? g_pre1 : g_pre2;
    const float* X = (MODE == 0) ? Xin : (g_hist1 + H1);

    __shared__ float Xs[16][64];
    __shared__ float Ws[16][64];

    int tid = threadIdx.x;
    int tx = tid & 15;
    int ty = tid >> 4;
    int n0 = blockIdx.x * 64;
    int m0 = blockIdx.y * 64;

    float acc[4][4];
#pragma unroll
    for (int i = 0; i < 4; i++)
#pragma unroll
        for (int j = 0; j < 4; j++) acc[i][j] = 0.0f;

    for (int kk = 0; kk < K; kk += 16) {
#pragma unroll
        for (int i = tid; i < 1024; i += 256) {
            int r = i >> 4;
            int k = i & 15;
            Xs[k][r] = X[(size_t)(m0 + r) * K + kk + k];
            Ws[k][r] = W[(size_t)(n0 + r) * K + kk + k];
        }
        __syncthreads();
#pragma unroll
        for (int k = 0; k < 16; k++) {
            float4 a = *(const float4*)&Xs[k][ty * 4];
            float4 b = *(const float4*)&Ws[k][tx * 4];
            float av[4] = {a.x, a.y, a.z, a.w};
            float bv[4] = {b.x, b.y, b.z, b.w};
#pragma unroll
            for (int i = 0; i < 4; i++)
#pragma unroll
                for (int j = 0; j < 4; j++) acc[i][j] = fmaf(av[i], bv[j], acc[i][j]);
        }
        __syncthreads();
    }

#pragma unroll
    for (int i = 0; i < 4; i++) {
        int m = m0 + ty * 4 + i;
#pragma unroll
        for (int j = 0; j < 4; j++) {
            int n = n0 + tx * 4 + j;
            C[(size_t)m * N + n] = acc[i][j] + ba[n] + bb[n];
        }
    }
}

// ---------------- persistent LSTM recurrence ----------------
// 128 CTAs, single co-resident wave. One warp owns one hidden unit; cell state c
// lives in a lane-0 register across all 4096 steps. h history is write-once.
// Weights: columns [0,CSM) in SMEM (preloaded once); columns [CSM,HD) streamed,
// prefetched into regs BEFORE the barrier wait.
// Barrier: one MONOTONIC flag per CTA, padded to its own 128B line. CTA b stores
// t+1 after step t; waiter thread p spins until flags[p*FPAD] >= t. No per-step
// reset, no shared-line contention, max skew 1 step (safe with write-once hist).
template <int HD, int PHASE, int CSM>
__global__ void __launch_bounds__(HD / 4, 1)
lstm_kernel() {
    constexpr int WARPS = HD / 128;          // warps per CTA = units per CTA
    constexpr int NSM   = CSM / 4;           // smem uint2 per gate row
    constexpr int NST   = (HD - CSM) / 4;    // streamed uint2 per gate row
    constexpr int ISM   = NSM / 32;
    constexpr int IST   = NST / 32;

    const float* pre  = (PHASE == 0) ? g_pre1  : g_pre2;
    float*       hist = (PHASE == 0) ? g_hist1 : g_hist2;
    unsigned*    flags= (PHASE == 0) ? g_flags1: g_flags2;
    const uint2* whh  = (PHASE == 0) ? g_whh1h : g_whh2h;

    extern __shared__ char smem_raw[];
    uint2*  wsm = (uint2*)smem_raw;                                  // [WARPS*4*NSM]
    float4* hs  = (float4*)(smem_raw + (size_t)WARPS * 4 * NSM * 8); // [HD/4]

    int tid  = threadIdx.x;
    int wid  = tid >> 5;
    int lane = tid & 31;
    int u = blockIdx.x * WARPS + wid;

    // ---- preload SMEM-resident weight columns (once) ----
    for (int idx = tid; idx < WARPS * 4 * NSM; idx += blockDim.x) {
        int row = idx / NSM;             // w*4 + g
        int col = idx - row * NSM;
        int w = row >> 2, g = row & 3;
        int uu = blockIdx.x * WARPS + w;
        wsm[idx] = whh[(size_t)(g * HD + uu) * (HD / 4) + col];
    }
    __syncthreads();

    // streamed-region global pointers (per warp, per gate)
    const uint2* wst0 = whh + (size_t)(0 * HD + u) * (HD / 4) + NSM;
    const uint2* wst1 = whh + (size_t)(1 * HD + u) * (HD / 4) + NSM;
    const uint2* wst2 = whh + (size_t)(2 * HD + u) * (HD / 4) + NSM;
    const uint2* wst3 = whh + (size_t)(3 * HD + u) * (HD / 4) + NSM;

    const uint2* wsm0 = wsm + (size_t)(wid * 4 + 0) * NSM;
    const uint2* wsm1 = wsm + (size_t)(wid * 4 + 1) * NSM;
    const uint2* wsm2 = wsm + (size_t)(wid * 4 + 2) * NSM;
    const uint2* wsm3 = wsm + (size_t)(wid * 4 + 3) * NSM;

    float c = 0.0f;

    for (int t = 0; t < T_STEPS; t++) {
        // ---- prefetch streamed weights (step-invariant, no barrier dependency) ----
        uint2 sw0[IST > 0 ? IST : 1], sw1[IST > 0 ? IST : 1];
        uint2 sw2[IST > 0 ? IST : 1], sw3[IST > 0 ? IST : 1];
        if (IST > 0) {
#pragma unroll
            for (int i = 0; i < IST; i++) {
                int j = (i << 5) + lane;
                sw0[i] = wst0[j]; sw1[i] = wst1[j];
                sw2[i] = wst2[j]; sw3[i] = wst3[j];
            }
        }

        // ---- distributed barrier: thread p polls CTA p's monotonic counter ----
        if (t > 0 && tid < NCTA) {
            while (ld_acq_u32(&flags[tid * FPAD]) < (unsigned)t) {
                __nanosleep(32);
            }
        }
        __syncthreads();

        // ---- stage h_prev (slot t) into SMEM, L1-bypassed ----
        hs[tid] = ld_cg_f4((const float4*)(hist + (size_t)t * HD) + tid);
        __syncthreads();

        // ---- gate dot products: SMEM part ----
        float a0 = 0.f, a1 = 0.f, a2 = 0.f, a3 = 0.f;
#pragma unroll
        for (int i = 0; i < ISM; i++) {
            int c4 = (i << 5) + lane;
            float4 h4 = hs[c4];
            {
                uint2 p = wsm0[c4];
                float2 lo = __half22float2(*reinterpret_cast<__half2*>(&p.x));
                float2 hi = __half22float2(*reinterpret_cast<__half2*>(&p.y));
                a0 = fmaf(lo.x, h4.x, a0); a0 = fmaf(lo.y, h4.y, a0);
                a0 = fmaf(hi.x, h4.z, a0); a0 = fmaf(hi.y, h4.w, a0);
            }
            {
                uint2 p = wsm1[c4];
                float2 lo = __half22float2(*reinterpret_cast<__half2*>(&p.x));
                float2 hi = __half22float2(*reinterpret_cast<__half2*>(&p.y));
                a1 = fmaf(lo.x, h4.x, a1); a1 = fmaf(lo.y, h4.y, a1);
                a1 = fmaf(hi.x, h4.z, a1); a1 = fmaf(hi.y, h4.w, a1);
            }
            {
                uint2 p = wsm2[c4];
                float2 lo = __half22float2(*reinterpret_cast<__half2*>(&p.x));
                float2 hi = __half22float2(*reinterpret_cast<__half2*>(&p.y));
                a2 = fmaf(lo.x, h4.x, a2); a2 = fmaf(lo.y, h4.y, a2);
                a2 = fmaf(hi.x, h4.z, a2); a2 = fmaf(hi.y, h4.w, a2);
            }
            {
                uint2 p = wsm3[c4];
                float2 lo = __half22float2(*reinterpret_cast<__half2*>(&p.x));
                float2 hi = __half22float2(*reinterpret_cast<__half2*>(&p.y));
                a3 = fmaf(lo.x, h4.x, a3); a3 = fmaf(lo.y, h4.y, a3);
                a3 = fmaf(hi.x, h4.z, a3); a3 = fmaf(hi.y, h4.w, a3);
            }
        }
        // ---- streamed part (registers already loaded) ----
        if (IST > 0) {
#pragma unroll
            for (int i = 0; i < IST; i++) {
                int c4 = NSM + (i << 5) + lane;
                float4 h4 = hs[c4];
                {
                    float2 lo = __half22float2(*reinterpret_cast<__half2*>(&sw0[i].x));
                    float2 hi = __half22float2(*reinterpret_cast<__half2*>(&sw0[i].y));
                    a0 = fmaf(lo.x, h4.x, a0); a0 = fmaf(lo.y, h4.y, a0);
                    a0 = fmaf(hi.x, h4.z, a0); a0 = fmaf(hi.y, h4.w, a0);
                }
                {
                    float2 lo = __half22float2(*reinterpret_cast<__half2*>(&sw1[i].x));
                    float2 hi = __half22float2(*reinterpret_cast<__half2*>(&sw1[i].y));
                    a1 = fmaf(lo.x, h4.x, a1); a1 = fmaf(lo.y, h4.y, a1);
                    a1 = fmaf(hi.x, h4.z, a1); a1 = fmaf(hi.y, h4.w, a1);
                }
                {
                    float2 lo = __half22float2(*reinterpret_cast<__half2*>(&sw2[i].x));
                    float2 hi = __half22float2(*reinterpret_cast<__half2*>(&sw2[i].y));
                    a2 = fmaf(lo.x, h4.x, a2); a2 = fmaf(lo.y, h4.y, a2);
                    a2 = fmaf(hi.x, h4.z, a2); a2 = fmaf(hi.y, h4.w, a2);
                }
                {
                    float2 lo = __half22float2(*reinterpret_cast<__half2*>(&sw3[i].x));
                    float2 hi = __half22float2(*reinterpret_cast<__half2*>(&sw3[i].y));
                    a3 = fmaf(lo.x, h4.x, a3); a3 = fmaf(lo.y, h4.y, a3);
                    a3 = fmaf(hi.x, h4.z, a3); a3 = fmaf(hi.y, h4.w, a3);
                }
            }
        }
#pragma unroll
        for (int off = 16; off > 0; off >>= 1) {
            a0 += __shfl_xor_sync(0xFFFFFFFFu, a0, off);
            a1 += __shfl_xor_sync(0xFFFFFFFFu, a1, off);
            a2 += __shfl_xor_sync(0xFFFFFFFFu, a2, off);
            a3 += __shfl_xor_sync(0xFFFFFFFFu, a3, off);
        }

        // ---- state update + publish h into write-once slot t+1 ----
        if (lane == 0) {
            const float* prow = pre + (size_t)t * (4 * HD);
            float pi = prow[0 * HD + u] + a0;
            float pf = prow[1 * HD + u] + a1;
            float pg = prow[2 * HD + u] + a2;
            float po = prow[3 * HD + u] + a3;
            float iv = sigmoidf_(pi);
            float fv = sigmoidf_(pf);
            float gv = tanhf(pg);
            float ov = sigmoidf_(po);
            c = fv * c + iv * gv;
            float h = ov * tanhf(c);
            st_cg_f32(hist + (size_t)(t + 1) * HD + u, h);
        }

        // ---- release: each storer drains its own store; ONE flag store per CTA ----
        __threadfence();
        __syncthreads();
        if (tid == 0) {
            st_rel_u32(&flags[blockIdx.x * FPAD], (unsigned)(t + 1));
        }
    }
}

// ---------------- head: two matvecs on final h2 (slot T of g_hist2) ----------------
__global__ void __launch_bounds__(256) head1_kernel(const float* __restrict__ w,
                                                    const float* __restrict__ b) {
    int wid = threadIdx.x >> 5, lane = threadIdx.x & 31;
    int o = blockIdx.x * 8 + wid;
    const float4* wr = (const float4*)(w + (size_t)o * H2);
    const float4* hv = (const float4*)(g_hist2 + (size_t)T_STEPS * H2);
    float a = 0.f;
#pragma unroll
    for (int i = 0; i < 16; i++) {
        float4 W4 = wr[(i << 5) + lane];
        float4 Hh = hv[(i << 5) + lane];
        a = fmaf(W4.x, Hh.x, a); a = fmaf(W4.y, Hh.y, a);
        a = fmaf(W4.z, Hh.z, a); a = fmaf(W4.w, Hh.w, a);
    }
#pragma unroll
    for (int off = 16; off > 0; off >>= 1) a += __shfl_xor_sync(0xFFFFFFFFu, a, off);
    if (lane == 0) g_mid[o] = a + b[o];
}

__global__ void __launch_bounds__(256) head2_kernel(const float* __restrict__ w,
                                                    const float* __restrict__ b,
                                                    float* __restrict__ out) {
    int wid = threadIdx.x >> 5, lane = threadIdx.x & 31;
    int o = blockIdx.x * 8 + wid;
    const float4* wr = (const float4*)(w + (size_t)o * (2 * OUT_SZ));
    const float4* mv = (const float4*)(g_mid);
    float a = 0.f;
#pragma unroll
    for (int i = 0; i < 8; i++) {
        float4 W4 = wr[(i << 5) + lane];
        float4 Mm = mv[(i << 5) + lane];
        a = fmaf(W4.x, Mm.x, a); a = fmaf(W4.y, Mm.y, a);
        a = fmaf(W4.z, Mm.z, a); a = fmaf(W4.w, Mm.w, a);
    }
#pragma unroll
    for (int off = 16; off > 0; off >>= 1) a += __shfl_xor_sync(0xFFFFFFFFu, a, off);
    if (lane == 0) out[o] = a + b[o];
}

// ---------------- launch ----------------
extern "C" void kernel_launch(void* const* d_in, const int* in_sizes, int n_in,
                              void* d_out, int out_size) {
    const float* input_seq = (const float*)d_in[0];
    const float* w_ih1     = (const float*)d_in[1];
    const float* w_hh1     = (const float*)d_in[2];
    const float* b_ih1     = (const float*)d_in[3];
    const float* b_hh1     = (const float*)d_in[4];
    const float* w_ih2     = (const float*)d_in[5];
    const float* w_hh2     = (const float*)d_in[6];
    const float* b_ih2     = (const float*)d_in[7];
    const float* b_hh2     = (const float*)d_in[8];
    const float* w_l1      = (const float*)d_in[9];
    const float* b_l1      = (const float*)d_in[10];
    const float* w_l2      = (const float*)d_in[11];
    const float* b_l2      = (const float*)d_in[12];
    float* out = (float*)d_out;

    constexpr int SMEM1 = (H1 / 128) * 4 * (CSM1 / 4) * 8 + H1 * 4;   //  69632 B
    constexpr int SMEM2 = (H2 / 128) * 4 * (CSM2 / 4) * 8 + H2 * 4;   // 221184 B

    static bool attr_done = false;
    if (!attr_done) {
        cudaFuncSetAttribute(lstm_kernel<H1, 0, CSM1>,
                             cudaFuncAttributeMaxDynamicSharedMemorySize, SMEM1);
        cudaFuncSetAttribute(lstm_kernel<H2, 1, CSM2>,
                             cudaFuncAttributeMaxDynamicSharedMemorySize, SMEM2);
        attr_done = true;
    }

    // 1) reset flags + zero h0 slots; convert recurrent weights to fp16
    init_kernel<<<16, 256>>>();
    convert_w_kernel<<<4096, 256>>>(w_hh1, w_hh2);

    // 2) lstm1 input projection: g_pre1[T, 4*H1]
    {
        dim3 grid(4 * H1 / 64, T_STEPS / 64);
        gemm_bias_kernel<0><<<grid, 256>>>(input_seq, w_ih1, b_ih1, b_hh1,
                                           4 * H1, IN_SZ);
    }

    // 3) lstm1 recurrence (persistent, 128 CTAs x 256 threads, full SMEM weights)
    lstm_kernel<H1, 0, CSM1><<<NCTA, H1 / 4, SMEM1>>>();

    // 4) lstm2 input projection: g_pre2[T, 4*H2] from h1 history
    {
        dim3 grid(4 * H2 / 64, T_STEPS / 64);
        gemm_bias_kernel<1><<<grid, 256>>>(nullptr, w_ih2, b_ih2, b_hh2,
                                           4 * H2, H1);
    }

    // 5) lstm2 recurrence (persistent, 128 CTAs x 512 threads, 13/16 SMEM weights)
    lstm_kernel<H2, 1, CSM2><<<NCTA, H2 / 4, SMEM2>>>();

    // 6) head on final h2
    head1_kernel<<<128, 256>>>(w_l1, b_l1);
    head2_kernel<<<64, 256>>>(w_l2, b_l2, out);
}

// round 13
// speedup vs baseline: 1.8604x; 1.0718x over previous
#include <cuda_runtime.h>
#include <cuda_fp16.h>
#include <math.h>

#define T_STEPS 4096
#define IN_SZ   512
#define H1      1024
#define H2      2048
#define OUT_SZ  512
#define NCTA    128

#define CSM1    1024    // lstm1: all columns SMEM-resident
#define CSM2    1664    // lstm2: 13/16 of columns SMEM-resident

#define FPAD    32      // flag padding: 32 u32 = 128 B -> one L2 line per CTA flag

// ---------------- device scratch (static, no allocation) ----------------
__device__ float g_pre1[T_STEPS * 4 * H1];        //  64 MB
__device__ float g_pre2[T_STEPS * 4 * H2];        // 128 MB
__device__ float g_hist1[(T_STEPS + 1) * H1];     //  slot t = h[t-1], slot 0 = zeros
__device__ float g_hist2[(T_STEPS + 1) * H2];
__device__ float g_mid[2 * OUT_SZ];
__device__ unsigned g_flags1[NCTA * FPAD];        // monotonic step counters, line-padded
__device__ unsigned g_flags2[NCTA * FPAD];

// fp16 copies of recurrent weights, packed 4 halfs per uint2
__device__ uint2 g_whh1h[(size_t)4 * H1 * H1 / 4];   //  8 MB
__device__ uint2 g_whh2h[(size_t)4 * H2 * H2 / 4];   // 32 MB

// ---------------- helpers ----------------
__device__ __forceinline__ unsigned ld_acq_u32(const unsigned* p) {
    unsigned v;
    asm volatile("ld.acquire.gpu.global.u32 %0, [%1];" : "=r"(v) : "l"(p));
    return v;
}

__device__ __forceinline__ void st_rel_u32(unsigned* p, unsigned v) {
    asm volatile("st.release.gpu.global.u32 [%0], %1;" :: "l"(p), "r"(v));
}

__device__ __forceinline__ float4 ld_cg_f4(const float4* p) {
    float4 v;
    asm volatile("ld.global.cg.v4.f32 {%0,%1,%2,%3}, [%4];"
                 : "=f"(v.x), "=f"(v.y), "=f"(v.z), "=f"(v.w) : "l"(p));
    return v;
}

__device__ __forceinline__ float ld_cg_f32(const float* p) {
    float v;
    asm volatile("ld.global.cg.f32 %0, [%1];" : "=f"(v) : "l"(p));
    return v;
}

__device__ __forceinline__ void st_cg_f32(float* p, float v) {
    asm volatile("st.global.cg.f32 [%0], %1;" :: "l"(p), "f"(v));
}

// MUFU-based activations: EX2 + RCP.approx (rel err ~1e-6, ~5 instr each)
__device__ __forceinline__ float fast_rcp(float x) {
    float r;
    asm("rcp.approx.f32 %0, %1;" : "=f"(r) : "f"(x));
    return r;
}
__device__ __forceinline__ float fast_sig(float x) {
    return fast_rcp(1.0f + __expf(-x));
}
__device__ __forceinline__ float fast_tanh(float x) {
    return fmaf(2.0f, fast_rcp(1.0f + __expf(-2.0f * x)), -1.0f);
}

// ---------------- init: zero flags + h0 slots (runs every replay) ----------------
__global__ void init_kernel() {
    int i = blockIdx.x * blockDim.x + threadIdx.x;
    if (i < NCTA * FPAD) { g_flags1[i] = 0u; g_flags2[i] = 0u; }
    if (i < H1) g_hist1[i] = 0.0f;
    if (i < H2) g_hist2[i] = 0.0f;
}

// ---------------- convert recurrent weights fp32 -> fp16 (once per replay) ----------------
__global__ void convert_w_kernel(const float* __restrict__ w1,
                                 const float* __restrict__ w2) {
    const size_t n1 = (size_t)4 * H1 * H1 / 4;
    const size_t n2 = (size_t)4 * H2 * H2 / 4;
    for (size_t i = (size_t)blockIdx.x * blockDim.x + threadIdx.x;
         i < n1 + n2; i += (size_t)gridDim.x * blockDim.x) {
        float4 v = (i < n1) ? ((const float4*)w1)[i] : ((const float4*)w2)[i - n1];
        __half2 lo = __floats2half2_rn(v.x, v.y);
        __half2 hi = __floats2half2_rn(v.z, v.w);
        uint2 o;
        o.x = *reinterpret_cast<unsigned*>(&lo);
        o.y = *reinterpret_cast<unsigned*>(&hi);
        if (i < n1) g_whh1h[i] = o;
        else        g_whh2h[i - n1] = o;
    }
}

// ---------------- input-projection GEMM: C[M,N] = X[M,K] * W[N,K]^T + ba + bb ----------------
template <int MODE>
__global__ void __launch_bounds__(256, 2)
gemm_bias_kernel(const float* __restrict__ Xin, const float* __restrict__ W,
                 const float* __restrict__ ba, const float* __restrict__ bb,
                 int N, int K) {
    float* C = (MODE == 0) ? g_pre1 : g_pre2;
    const float* X = (MODE == 0) ? Xin : (g_hist1 + H1);

    __shared__ float Xs[16][64];
    __shared__ float Ws[16][64];

    int tid = threadIdx.x;
    int tx = tid & 15;
    int ty = tid >> 4;
    int n0 = blockIdx.x * 64;
    int m0 = blockIdx.y * 64;

    float acc[4][4];
#pragma unroll
    for (int i = 0; i < 4; i++)
#pragma unroll
        for (int j = 0; j < 4; j++) acc[i][j] = 0.0f;

    for (int kk = 0; kk < K; kk += 16) {
#pragma unroll
        for (int i = tid; i < 1024; i += 256) {
            int r = i >> 4;
            int k = i & 15;
            Xs[k][r] = X[(size_t)(m0 + r) * K + kk + k];
            Ws[k][r] = W[(size_t)(n0 + r) * K + kk + k];
        }
        __syncthreads();
#pragma unroll
        for (int k = 0; k < 16; k++) {
            float4 a = *(const float4*)&Xs[k][ty * 4];
            float4 b = *(const float4*)&Ws[k][tx * 4];
            float av[4] = {a.x, a.y, a.z, a.w};
            float bv[4] = {b.x, b.y, b.z, b.w};
#pragma unroll
            for (int i = 0; i < 4; i++)
#pragma unroll
                for (int j = 0; j < 4; j++) acc[i][j] = fmaf(av[i], bv[j], acc[i][j]);
        }
        __syncthreads();
    }

#pragma unroll
    for (int i = 0; i < 4; i++) {
        int m = m0 + ty * 4 + i;
#pragma unroll
        for (int j = 0; j < 4; j++) {
            int n = n0 + tx * 4 + j;
            C[(size_t)m * N + n] = acc[i][j] + ba[n] + bb[n];
        }
    }
}

// ---------------- persistent LSTM recurrence ----------------
// 128 CTAs, single co-resident wave. One warp owns one hidden unit; cell state c
// lives in a lane-0 register across all 4096 steps. h history is write-once.
// Per step: prefetch (streamed weights + pre row) BEFORE the barrier; poller p
// spins on CTA p's monotonic flag then immediately gathers CTA p's h chunk
// (acquire orders the loads); one __syncthreads; dot products (SMEM + reg
// weights); shuffle reduce; MUFU activations; h store; __syncthreads; tid0
// release-stores the flag (CG cumulativity pattern — no per-thread membar).
template <int HD, int PHASE, int CSM>
__global__ void __launch_bounds__(HD / 4, 1)
lstm_kernel() {
    constexpr int WARPS = HD / 128;          // warps per CTA = units per CTA
    constexpr int NSM   = CSM / 4;           // smem uint2 per gate row
    constexpr int IST   = (HD - CSM) / 128;  // streamed uint2 iters (per 32 lanes)
    constexpr int ISM   = NSM / 32;
    constexpr int CH4   = WARPS / 4;         // float4 per CTA's h chunk

    const float* pre  = (PHASE == 0) ? g_pre1  : g_pre2;
    float*       hist = (PHASE == 0) ? g_hist1 : g_hist2;
    unsigned*    flags= (PHASE == 0) ? g_flags1: g_flags2;
    const uint2* whh  = (PHASE == 0) ? g_whh1h : g_whh2h;

    extern __shared__ char smem_raw[];
    uint2*  wsm = (uint2*)smem_raw;                                  // [WARPS*4*NSM]
    float4* hs  = (float4*)(smem_raw + (size_t)WARPS * 4 * NSM * 8); // [HD/4]

    int tid  = threadIdx.x;
    int wid  = tid >> 5;
    int lane = tid & 31;
    int u = blockIdx.x * WARPS + wid;

    // ---- preload SMEM-resident weight columns (once) ----
    for (int idx = tid; idx < WARPS * 4 * NSM; idx += blockDim.x) {
        int row = idx / NSM;             // w*4 + g
        int col = idx - row * NSM;
        int w = row >> 2, g = row & 3;
        int uu = blockIdx.x * WARPS + w;
        wsm[idx] = whh[(size_t)(g * HD + uu) * (HD / 4) + col];
    }
    __syncthreads();

    // streamed-region global pointers (per warp, per gate)
    const uint2* wst0 = whh + (size_t)(0 * HD + u) * (HD / 4) + NSM;
    const uint2* wst1 = whh + (size_t)(1 * HD + u) * (HD / 4) + NSM;
    const uint2* wst2 = whh + (size_t)(2 * HD + u) * (HD / 4) + NSM;
    const uint2* wst3 = whh + (size_t)(3 * HD + u) * (HD / 4) + NSM;

    const uint2* wsm0 = wsm + (size_t)(wid * 4 + 0) * NSM;
    const uint2* wsm1 = wsm + (size_t)(wid * 4 + 1) * NSM;
    const uint2* wsm2 = wsm + (size_t)(wid * 4 + 2) * NSM;
    const uint2* wsm3 = wsm + (size_t)(wid * 4 + 3) * NSM;

    float c = 0.0f;

    for (int t = 0; t < T_STEPS; t++) {
        // ---- prefetch streamed weights (no barrier dependency) ----
        uint2 sw0[IST > 0 ? IST : 1], sw1[IST > 0 ? IST : 1];
        uint2 sw2[IST > 0 ? IST : 1], sw3[IST > 0 ? IST : 1];
        if (IST > 0) {
#pragma unroll
            for (int i = 0; i < IST; i++) {
                int j = (i << 5) + lane;
                sw0[i] = wst0[j]; sw1[i] = wst1[j];
                sw2[i] = wst2[j]; sw3[i] = wst3[j];
            }
        }
        // ---- prefetch pre-activations for this step (DRAM; hides under spin) ----
        float pp0 = 0.f, pp1 = 0.f, pp2 = 0.f, pp3 = 0.f;
        if (lane == 0) {
            const float* prow = pre + (size_t)t * (4 * HD);
            pp0 = ld_cg_f32(prow + 0 * HD + u);
            pp1 = ld_cg_f32(prow + 1 * HD + u);
            pp2 = ld_cg_f32(prow + 2 * HD + u);
            pp3 = ld_cg_f32(prow + 3 * HD + u);
        }

        // ---- fused barrier + h gather: poller p waits on CTA p, then loads its chunk ----
        if (tid < NCTA) {
            if (t > 0) {
                while (ld_acq_u32(&flags[tid * FPAD]) < (unsigned)t) { }
            }
            const float4* src = (const float4*)(hist + (size_t)t * HD) + tid * CH4;
#pragma unroll
            for (int j = 0; j < CH4; j++) {
                hs[tid * CH4 + j] = ld_cg_f4(src + j);
            }
        }
        __syncthreads();

        // ---- gate dot products: SMEM part ----
        float a0 = 0.f, a1 = 0.f, a2 = 0.f, a3 = 0.f;
#pragma unroll
        for (int i = 0; i < ISM; i++) {
            int c4 = (i << 5) + lane;
            float4 h4 = hs[c4];
            {
                uint2 p = wsm0[c4];
                float2 lo = __half22float2(*reinterpret_cast<__half2*>(&p.x));
                float2 hi = __half22float2(*reinterpret_cast<__half2*>(&p.y));
                a0 = fmaf(lo.x, h4.x, a0); a0 = fmaf(lo.y, h4.y, a0);
                a0 = fmaf(hi.x, h4.z, a0); a0 = fmaf(hi.y, h4.w, a0);
            }
            {
                uint2 p = wsm1[c4];
                float2 lo = __half22float2(*reinterpret_cast<__half2*>(&p.x));
                float2 hi = __half22float2(*reinterpret_cast<__half2*>(&p.y));
                a1 = fmaf(lo.x, h4.x, a1); a1 = fmaf(lo.y, h4.y, a1);
                a1 = fmaf(hi.x, h4.z, a1); a1 = fmaf(hi.y, h4.w, a1);
            }
            {
                uint2 p = wsm2[c4];
                float2 lo = __half22float2(*reinterpret_cast<__half2*>(&p.x));
                float2 hi = __half22float2(*reinterpret_cast<__half2*>(&p.y));
                a2 = fmaf(lo.x, h4.x, a2); a2 = fmaf(lo.y, h4.y, a2);
                a2 = fmaf(hi.x, h4.z, a2); a2 = fmaf(hi.y, h4.w, a2);
            }
            {
                uint2 p = wsm3[c4];
                float2 lo = __half22float2(*reinterpret_cast<__half2*>(&p.x));
                float2 hi = __half22float2(*reinterpret_cast<__half2*>(&p.y));
                a3 = fmaf(lo.x, h4.x, a3); a3 = fmaf(lo.y, h4.y, a3);
                a3 = fmaf(hi.x, h4.z, a3); a3 = fmaf(hi.y, h4.w, a3);
            }
        }
        // ---- streamed part (registers already loaded) ----
        if (IST > 0) {
#pragma unroll
            for (int i = 0; i < IST; i++) {
                int c4 = NSM + (i << 5) + lane;
                float4 h4 = hs[c4];
                {
                    float2 lo = __half22float2(*reinterpret_cast<__half2*>(&sw0[i].x));
                    float2 hi = __half22float2(*reinterpret_cast<__half2*>(&sw0[i].y));
                    a0 = fmaf(lo.x, h4.x, a0); a0 = fmaf(lo.y, h4.y, a0);
                    a0 = fmaf(hi.x, h4.z, a0); a0 = fmaf(hi.y, h4.w, a0);
                }
                {
                    float2 lo = __half22float2(*reinterpret_cast<__half2*>(&sw1[i].x));
                    float2 hi = __half22float2(*reinterpret_cast<__half2*>(&sw1[i].y));
                    a1 = fmaf(lo.x, h4.x, a1); a1 = fmaf(lo.y, h4.y, a1);
                    a1 = fmaf(hi.x, h4.z, a1); a1 = fmaf(hi.y, h4.w, a1);
                }
                {
                    float2 lo = __half22float2(*reinterpret_cast<__half2*>(&sw2[i].x));
                    float2 hi = __half22float2(*reinterpret_cast<__half2*>(&sw2[i].y));
                    a2 = fmaf(lo.x, h4.x, a2); a2 = fmaf(lo.y, h4.y, a2);
                    a2 = fmaf(hi.x, h4.z, a2); a2 = fmaf(hi.y, h4.w, a2);
                }
                {
                    float2 lo = __half22float2(*reinterpret_cast<__half2*>(&sw3[i].x));
                    float2 hi = __half22float2(*reinterpret_cast<__half2*>(&sw3[i].y));
                    a3 = fmaf(lo.x, h4.x, a3); a3 = fmaf(lo.y, h4.y, a3);
                    a3 = fmaf(hi.x, h4.z, a3); a3 = fmaf(hi.y, h4.w, a3);
                }
            }
        }
#pragma unroll
        for (int off = 16; off > 0; off >>= 1) {
            a0 += __shfl_xor_sync(0xFFFFFFFFu, a0, off);
            a1 += __shfl_xor_sync(0xFFFFFFFFu, a1, off);
            a2 += __shfl_xor_sync(0xFFFFFFFFu, a2, off);
            a3 += __shfl_xor_sync(0xFFFFFFFFu, a3, off);
        }

        // ---- state update + publish h into write-once slot t+1 ----
        if (lane == 0) {
            float iv = fast_sig(pp0 + a0);
            float fv = fast_sig(pp1 + a1);
            float gv = fast_tanh(pp2 + a2);
            float ov = fast_sig(pp3 + a3);
            c = fv * c + iv * gv;
            float h = ov * fast_tanh(c);
            st_cg_f32(hist + (size_t)(t + 1) * HD + u, h);
        }

        // ---- release: CTA-scope sync orders all lane0 stores before tid0's
        //      gpu-scope release store (cooperative-groups cumulativity pattern) ----
        __syncthreads();
        if (tid == 0) {
            st_rel_u32(&flags[blockIdx.x * FPAD], (unsigned)(t + 1));
        }
    }
}

// ---------------- head: two matvecs on final h2 (slot T of g_hist2) ----------------
__global__ void __launch_bounds__(256) head1_kernel(const float* __restrict__ w,
                                                    const float* __restrict__ b) {
    int wid = threadIdx.x >> 5, lane = threadIdx.x & 31;
    int o = blockIdx.x * 8 + wid;
    const float4* wr = (const float4*)(w + (size_t)o * H2);
    const float4* hv = (const float4*)(g_hist2 + (size_t)T_STEPS * H2);
    float a = 0.f;
#pragma unroll
    for (int i = 0; i < 16; i++) {
        float4 W4 = wr[(i << 5) + lane];
        float4 Hh = hv[(i << 5) + lane];
        a = fmaf(W4.x, Hh.x, a); a = fmaf(W4.y, Hh.y, a);
        a = fmaf(W4.z, Hh.z, a); a = fmaf(W4.w, Hh.w, a);
    }
#pragma unroll
    for (int off = 16; off > 0; off >>= 1) a += __shfl_xor_sync(0xFFFFFFFFu, a, off);
    if (lane == 0) g_mid[o] = a + b[o];
}

__global__ void __launch_bounds__(256) head2_kernel(const float* __restrict__ w,
                                                    const float* __restrict__ b,
                                                    float* __restrict__ out) {
    int wid = threadIdx.x >> 5, lane = threadIdx.x & 31;
    int o = blockIdx.x * 8 + wid;
    const float4* wr = (const float4*)(w + (size_t)o * (2 * OUT_SZ));
    const float4* mv = (const float4*)(g_mid);
    float a = 0.f;
#pragma unroll
    for (int i = 0; i < 8; i++) {
        float4 W4 = wr[(i << 5) + lane];
        float4 Mm = mv[(i << 5) + lane];
        a = fmaf(W4.x, Mm.x, a); a = fmaf(W4.y, Mm.y, a);
        a = fmaf(W4.z, Mm.z, a); a = fmaf(W4.w, Mm.w, a);
    }
#pragma unroll
    for (int off = 16; off > 0; off >>= 1) a += __shfl_xor_sync(0xFFFFFFFFu, a, off);
    if (lane == 0) out[o] = a + b[o];
}

// ---------------- launch ----------------
extern "C" void kernel_launch(void* const* d_in, const int* in_sizes, int n_in,
                              void* d_out, int out_size) {
    const float* input_seq = (const float*)d_in[0];
    const float* w_ih1     = (const float*)d_in[1];
    const float* w_hh1     = (const float*)d_in[2];
    const float* b_ih1     = (const float*)d_in[3];
    const float* b_hh1     = (const float*)d_in[4];
    const float* w_ih2     = (const float*)d_in[5];
    const float* w_hh2     = (const float*)d_in[6];
    const float* b_ih2     = (const float*)d_in[7];
    const float* b_hh2     = (const float*)d_in[8];
    const float* w_l1      = (const float*)d_in[9];
    const float* b_l1      = (const float*)d_in[10];
    const float* w_l2      = (const float*)d_in[11];
    const float* b_l2      = (const float*)d_in[12];
    float* out = (float*)d_out;

    constexpr int SMEM1 = (H1 / 128) * 4 * (CSM1 / 4) * 8 + H1 * 4;   //  69632 B
    constexpr int SMEM2 = (H2 / 128) * 4 * (CSM2 / 4) * 8 + H2 * 4;   // 221184 B

    static bool attr_done = false;
    if (!attr_done) {
        cudaFuncSetAttribute(lstm_kernel<H1, 0, CSM1>,
                             cudaFuncAttributeMaxDynamicSharedMemorySize, SMEM1);
        cudaFuncSetAttribute(lstm_kernel<H2, 1, CSM2>,
                             cudaFuncAttributeMaxDynamicSharedMemorySize, SMEM2);
        attr_done = true;
    }

    // 1) reset flags + zero h0 slots; convert recurrent weights to fp16
    init_kernel<<<16, 256>>>();
    convert_w_kernel<<<4096, 256>>>(w_hh1, w_hh2);

    // 2) lstm1 input projection: g_pre1[T, 4*H1]
    {
        dim3 grid(4 * H1 / 64, T_STEPS / 64);
        gemm_bias_kernel<0><<<grid, 256>>>(input_seq, w_ih1, b_ih1, b_hh1,
                                           4 * H1, IN_SZ);
    }

    // 3) lstm1 recurrence (persistent, 128 CTAs x 256 threads, full SMEM weights)
    lstm_kernel<H1, 0, CSM1><<<NCTA, H1 / 4, SMEM1>>>();

    // 4) lstm2 input projection: g_pre2[T, 4*H2] from h1 history
    {
        dim3 grid(4 * H2 / 64, T_STEPS / 64);
        gemm_bias_kernel<1><<<grid, 256>>>(nullptr, w_ih2, b_ih2, b_hh2,
                                           4 * H2, H1);
    }

    // 5) lstm2 recurrence (persistent, 128 CTAs x 512 threads, 13/16 SMEM weights)
    lstm_kernel<H2, 1, CSM2><<<NCTA, H2 / 4, SMEM2>>>();

    // 6) head on final h2
    head1_kernel<<<128, 256>>>(w_l1, b_l1);
    head2_kernel<<<64, 256>>>(w_l2, b_l2, out);
}